// round 1
// baseline (speedup 1.0000x reference)
#include <cuda_runtime.h>
#include <math.h>

#define INC 64
#define HID 16
#define BATCHES 8
#define NMAX 300032   // N=300000 (+ pad row)

// ---- scratch (no allocations allowed) ----
__device__ float    g_segsum[BATCHES * INC];
__device__ unsigned g_segmax[BATCHES * INC];   // order-encoded float
__device__ float    g_count[BATCHES];
__device__ float    g_gate[BATCHES * INC];
__device__ float2   g_sm[NMAX];                // (mean, max) per point, + zero pad row

__device__ __forceinline__ unsigned encode_ord(float f) {
    unsigned b = __float_as_uint(f);
    return (b & 0x80000000u) ? ~b : (b ^ 0x80000000u);
}
__device__ __forceinline__ float decode_ord(unsigned u) {
    unsigned b = (u & 0x80000000u) ? (u ^ 0x80000000u) : ~u;
    return __uint_as_float(b);
}

// ---- K0: init scratch ----
__global__ void k_init(int n) {
    int t = threadIdx.x;
    if (t < BATCHES * INC) {
        g_segsum[t] = 0.f;
        g_segmax[t] = encode_ord(-INFINITY);
    }
    if (t < BATCHES) g_count[t] = 0.f;
    if (t == 0) g_sm[n] = make_float2(0.f, 0.f);  // pad row for missing neighbors
}

// ---- K1: per-batch segment sum/max of F (batch_idx is sorted -> rare flushes) ----
__global__ void k_seg(const float* __restrict__ F, const int* __restrict__ bidx,
                      int n, int chunk) {
    int c     = threadIdx.x & 63;   // channel
    int lane4 = threadIdx.x >> 6;   // 0..3 row lanes
    int start = blockIdx.x * chunk;
    int end   = min(start + chunk, n);

    float sum = 0.f, mx = -INFINITY, cnt = 0.f;
    int cur = -1;
    for (int r = start + lane4; r < end; r += 4) {
        int b = bidx[r];
        if (b != cur) {
            if (cur >= 0) {
                atomicAdd(&g_segsum[cur * INC + c], sum);
                atomicMax(&g_segmax[cur * INC + c], encode_ord(mx));
                if (c == 0) atomicAdd(&g_count[cur], cnt);
            }
            cur = b; sum = 0.f; mx = -INFINITY; cnt = 0.f;
        }
        float v = F[(long)r * INC + c];
        sum += v;
        mx = fmaxf(mx, v);
        cnt += 1.f;
    }
    if (cur >= 0) {
        atomicAdd(&g_segsum[cur * INC + c], sum);
        atomicMax(&g_segmax[cur * INC + c], encode_ord(mx));
        if (c == 0) atomicAdd(&g_count[cur], cnt);
    }
}

// ---- K2: tiny shared MLP -> per-batch channel gate (1 block) ----
__global__ void k_gate(const float* __restrict__ W1, const float* __restrict__ b1,
                       const float* __restrict__ W2, const float* __restrict__ b2) {
    __shared__ float h1a[BATCHES][HID], h1m[BATCHES][HID];
    int t = threadIdx.x;  // 128 threads
    if (t < BATCHES * HID) {
        int b = t / HID, j = t % HID;
        float sa = b1[j], sm = b1[j];
        float inv = 1.f / g_count[b];
        for (int c = 0; c < INC; c++) {
            float w    = W1[c * HID + j];
            float mean = g_segsum[b * INC + c] * inv;
            float mxv  = decode_ord(g_segmax[b * INC + c]);
            sa += mean * w;
            sm += mxv * w;
        }
        h1a[b][j] = fmaxf(sa, 0.f);
        h1m[b][j] = fmaxf(sm, 0.f);
    }
    __syncthreads();
    for (int t2 = t; t2 < BATCHES * INC; t2 += 128) {
        int b = t2 / INC, c = t2 % INC;
        float s = 2.f * b2[c];
        for (int j = 0; j < HID; j++)
            s += (h1a[b][j] + h1m[b][j]) * W2[j * INC + c];
        g_gate[t2] = 1.f / (1.f + expf(-s));
    }
}

// ---- K3: warp-per-row: z = F*gate ; sm = (mean_c z, max_c z) ----
__global__ void k_sm(const float* __restrict__ F, const int* __restrict__ bidx, int n) {
    int warp  = (blockIdx.x * blockDim.x + threadIdx.x) >> 5;
    int lane  = threadIdx.x & 31;
    int nwarp = (gridDim.x * blockDim.x) >> 5;
    for (int r = warp; r < n; r += nwarp) {
        int b = bidx[r];
        float2 f = ((const float2*)(F + (long)r * INC))[lane];
        float2 g = ((const float2*)(g_gate + b * INC))[lane];
        float z0 = f.x * g.x, z1 = f.y * g.y;
        float s = z0 + z1;
        float m = fmaxf(z0, z1);
        #pragma unroll
        for (int o = 16; o > 0; o >>= 1) {
            s += __shfl_xor_sync(0xffffffffu, s, o);
            m = fmaxf(m, __shfl_xor_sync(0xffffffffu, m, o));
        }
        if (lane == 0) g_sm[r] = make_float2(s * (1.f / 64.f), m);
    }
}

// ---- K4: warp-per-row: 27-neighbor gather conv -> spatial sigmoid -> out ----
__global__ void k_out(const float* __restrict__ F, const int* __restrict__ bidx,
                      const int* __restrict__ nbr, const float* __restrict__ conv_w,
                      float* __restrict__ out, int n) {
    __shared__ float sw[54];
    if (threadIdx.x < 54) sw[threadIdx.x] = conv_w[threadIdx.x];
    __syncthreads();

    int warp  = (blockIdx.x * blockDim.x + threadIdx.x) >> 5;
    int lane  = threadIdx.x & 31;
    int nwarp = (gridDim.x * blockDim.x) >> 5;
    for (int r = warp; r < n; r += nwarp) {
        float p = 0.f;
        if (lane < 27) {
            int idx  = nbr[(long)r * 27 + lane];
            float2 s = g_sm[idx];                      // L2-resident gather (2.4 MB)
            p = s.x * sw[lane * 2 + 0] + s.y * sw[lane * 2 + 1];
        }
        #pragma unroll
        for (int o = 16; o > 0; o >>= 1)
            p += __shfl_xor_sync(0xffffffffu, p, o);   // butterfly: all lanes get sum
        float sig = 1.f / (1.f + expf(-p));

        int b = bidx[r];
        float2 f = ((const float2*)(F + (long)r * INC))[lane];
        float2 g = ((const float2*)(g_gate + b * INC))[lane];
        ((float2*)(out + (long)r * INC))[lane] =
            make_float2(f.x * g.x * sig, f.y * g.y * sig);
    }
}

extern "C" void kernel_launch(void* const* d_in, const int* in_sizes, int n_in,
                              void* d_out, int out_size) {
    const float* F      = (const float*)d_in[0];
    const int*   bidx   = (const int*)d_in[1];
    const int*   nbr    = (const int*)d_in[2];
    const float* W1     = (const float*)d_in[3];
    const float* b1     = (const float*)d_in[4];
    const float* W2     = (const float*)d_in[5];
    const float* b2     = (const float*)d_in[6];
    const float* conv_w = (const float*)d_in[7];
    float* out = (float*)d_out;
    int n = in_sizes[1];   // batch_idx length = N

    k_init<<<1, 512>>>(n);

    const int chunk = 512;
    k_seg<<<(n + chunk - 1) / chunk, 256>>>(F, bidx, n, chunk);

    k_gate<<<1, 128>>>(W1, b1, W2, b2);

    int blocks = 148 * 8;  // grid-stride, warp per row
    k_sm<<<blocks, 256>>>(F, bidx, n);
    k_out<<<blocks, 256>>>(F, bidx, nbr, conv_w, out, n);
}